// round 1
// baseline (speedup 1.0000x reference)
#include <cuda_runtime.h>

// Problem constants (fixed shapes from reference)
#define TOKENS   16
#define OUTS     32
#define CH       4
#define DIM      64
#define TILE_B   16
#define NTHREADS 512
#define YBUF_ELEMS (TILE_B * TOKENS * DIM)   // 16384 floats per buffer
#define SMEM_BYTES (2 * YBUF_ELEMS * 4 + TOKENS * 16)

// Packed dual-FMA: {d.lo,d.hi} = {a.lo*b.lo+c.lo, a.hi*b.hi+c.hi}
__device__ __forceinline__ unsigned long long ffma2(unsigned long long a,
                                                    unsigned long long b,
                                                    unsigned long long c) {
    unsigned long long d;
    asm("fma.rn.f32x2 %0, %1, %2, %3;" : "=l"(d) : "l"(a), "l"(b), "l"(c));
    return d;
}

__device__ __forceinline__ float f2lo(unsigned long long v) {
    return __int_as_float((int)(unsigned)(v & 0xffffffffull));
}
__device__ __forceinline__ float f2hi(unsigned long long v) {
    return __int_as_float((int)(unsigned)(v >> 32));
}

__global__ __launch_bounds__(NTHREADS, 1)
void ftok_kernel(const float* __restrict__ x,    // [B, 4, 64]
                 const float* __restrict__ Wg,   // [16, 32, 64]
                 const float* __restrict__ bg,   // [16, 32]
                 const float* __restrict__ Wm,   // [16, 4]
                 float* __restrict__ out,        // [B, 16*32]
                 int ntiles)
{
    extern __shared__ float smem[];
    float*  ys  = smem;                                   // [2][16b][16t][64d]
    float4* wm4 = (float4*)(smem + 2 * YBUF_ELEMS);       // [16] merge weights

    const int tid = threadIdx.x;
    const int w   = tid >> 5;   // warp id: produce b_local = w, consume token t = w
    const int l   = tid & 31;   // lane: produce d-pair (2l,2l+1), consume output o = l

    if (tid < TOKENS) {
        wm4[tid] = make_float4(Wm[tid * 4 + 0], Wm[tid * 4 + 1],
                               Wm[tid * 4 + 2], Wm[tid * 4 + 3]);
    }

    // Register-resident generator weights for (token=w, out=l): 64 fp32 as 32 packed u64.
    unsigned long long wp[32];
    {
        const ulonglong2* g = (const ulonglong2*)(Wg + (size_t)(w * OUTS + l) * DIM);
        #pragma unroll
        for (int j = 0; j < 16; j++) {
            ulonglong2 v = g[j];
            wp[2 * j]     = v.x;
            wp[2 * j + 1] = v.y;
        }
    }

    // Effective bias: bg[t,o] * sum_c Wm[t,c]
    const float s_t  = Wm[w * 4 + 0] + Wm[w * 4 + 1] + Wm[w * 4 + 2] + Wm[w * 4 + 3];
    const float ceff = s_t * bg[w * OUTS + l];

    int tile = blockIdx.x;

    // Prologue: x registers for the first tile (this warp's batch row).
    float2 xr[CH];
    {
        const float2* xp = (const float2*)(x + ((size_t)tile * TILE_B + w) * (CH * DIM));
        #pragma unroll
        for (int c = 0; c < CH; c++) xr[c] = xp[c * (DIM / 2) + l];
    }

    __syncthreads();  // wm4 visible

    int buf = 0;
    for (; tile < ntiles; tile += gridDim.x, buf ^= 1) {
        // ---------- produce: y[b=w][t][2l,2l+1] for all 16 tokens ----------
        float* ybase = ys + buf * YBUF_ELEMS + w * (TOKENS * DIM);
        #pragma unroll 1
        for (int t = 0; t < TOKENS; t++) {
            float4 m = wm4[t];                       // broadcast LDS.128
            float ylo = m.x * xr[0].x;
            float yhi = m.x * xr[0].y;
            ylo = fmaf(m.y, xr[1].x, ylo);  yhi = fmaf(m.y, xr[1].y, yhi);
            ylo = fmaf(m.z, xr[2].x, ylo);  yhi = fmaf(m.z, xr[2].y, yhi);
            ylo = fmaf(m.w, xr[3].x, ylo);  yhi = fmaf(m.w, xr[3].y, yhi);
            ((float2*)(ybase + t * DIM))[l] = make_float2(ylo, yhi);  // STS.64
        }

        // Prefetch x for this block's next tile (latency hides under consume).
        const int nt = tile + gridDim.x;
        if (nt < ntiles) {
            const float2* xp = (const float2*)(x + ((size_t)nt * TILE_B + w) * (CH * DIM));
            #pragma unroll
            for (int c = 0; c < CH; c++) xr[c] = xp[c * (DIM / 2) + l];
        }

        __syncthreads();  // y[tile] ready; also guards buffer reuse (double buffer)

        // ---------- consume: token t=w, output o=l, all 16 batch rows ----------
        const float* ycons = ys + buf * YBUF_ELEMS;
        float* obase = out + ((size_t)tile * TILE_B) * (TOKENS * OUTS) + w * OUTS + l;
        #pragma unroll 1
        for (int bl = 0; bl < TILE_B; bl++) {
            const ulonglong2* yp =
                (const ulonglong2*)(ycons + (bl * TOKENS + w) * DIM);  // broadcast
            unsigned long long a0 = 0ull, a1 = 0ull;  // packed {0,0}
            #pragma unroll
            for (int j = 0; j < 16; j++) {
                ulonglong2 y = yp[j];                 // LDS.128, 1 wavefront
                a0 = ffma2(y.x, wp[2 * j],     a0);   // d = 4j, 4j+1
                a1 = ffma2(y.y, wp[2 * j + 1], a1);   // d = 4j+2, 4j+3
            }
            float r = (f2lo(a0) + f2hi(a0)) + (f2lo(a1) + f2hi(a1)) + ceff;
            r = fmaxf(r, 0.0f);
            obase[(size_t)bl * (TOKENS * OUTS)] = r;  // coalesced 128B per warp
        }
    }
}

extern "C" void kernel_launch(void* const* d_in, const int* in_sizes, int n_in,
                              void* d_out, int out_size) {
    const float* x  = (const float*)d_in[0];
    const float* Wg = (const float*)d_in[1];
    const float* bg = (const float*)d_in[2];
    const float* Wm = (const float*)d_in[3];
    float* out = (float*)d_out;

    const int B      = in_sizes[0] / (CH * DIM);   // 32768
    const int ntiles = B / TILE_B;                 // 2048

    cudaFuncSetAttribute(ftok_kernel,
                         cudaFuncAttributeMaxDynamicSharedMemorySize, SMEM_BYTES);

    int dev = 0, sms = 148;
    cudaGetDevice(&dev);
    cudaDeviceGetAttribute(&sms, cudaDevAttrMultiProcessorCount, dev);
    int grid = sms < ntiles ? sms : ntiles;        // persistent: 1 CTA/SM

    ftok_kernel<<<grid, NTHREADS, SMEM_BYTES>>>(x, Wg, bg, Wm, out, ntiles);
}